// round 15
// baseline (speedup 1.0000x reference)
#include <cuda_runtime.h>
#include <cuda_bf16.h>
#include <cuda_fp8.h>
#include <math.h>
#include <stdint.h>

// Problem shape: x[M,H], gate/up [I,H], down [H,I]
#define M_DIM 4096
#define H_DIM 4096
#define I_DIM 14336
#define KB_H (H_DIM / 128)   // 32
#define KB_I (I_DIM / 128)   // 112

// ---------------- scratch (device globals; no allocation) ----------------
__device__ uint8_t g_Aq[(size_t)M_DIM * H_DIM];     // e4m3 codes of quantized x
__device__ float   g_As[(size_t)M_DIM * KB_H];
__device__ uint8_t g_Wg[(size_t)I_DIM * H_DIM];     // e4m3 weight codes
__device__ uint8_t g_Wu[(size_t)I_DIM * H_DIM];
__device__ uint8_t g_Wd[(size_t)H_DIM * I_DIM];
__device__ uint8_t g_Hq[(size_t)M_DIM * I_DIM];     // e4m3 hidden codes
__device__ float   g_Hs[(size_t)M_DIM * KB_I];
__device__ int     g_wfmt;   // 0 = raw e4m3 bytes, 1 = float32, 2 = bfloat16

// ---------------- weight dtype detection (device-side, deterministic) ----------------
__global__ void detect_kernel(const void* __restrict__ w) {
    __shared__ int c32, c16;
    int t = threadIdx.x;
    if (t == 0) { c32 = 0; c16 = 0; }
    __syncthreads();
    const float* f = (const float*)w;
    const __nv_bfloat16* b = (const __nv_bfloat16*)w;
    int l32 = 0, l16 = 0;
    for (int i = t; i < 16384; i += 256) {
        float v = f[i];
        if (fabsf(v) <= 448.0f) l32++;
        float u = __bfloat162float(b[i]);
        if (fabsf(u) <= 448.0f) l16++;
    }
    atomicAdd(&c32, l32);
    atomicAdd(&c16, l16);
    __syncthreads();
    if (t == 0) {
        int fmt = 0;
        if (c32 >= 16056) fmt = 1;
        else if (c16 >= 16056) fmt = 2;
        g_wfmt = fmt;
    }
}

// ---------------- weight convert -> raw e4m3 codes (vectorized x4) ----------------
__global__ void convert_w_kernel(const void* __restrict__ src,
                                 uint8_t* __restrict__ dst, size_t n4) {
    int fmt = g_wfmt;
    size_t i = (size_t)blockIdx.x * blockDim.x + threadIdx.x;
    size_t stride = (size_t)gridDim.x * blockDim.x;
    uchar4* d4 = (uchar4*)dst;
    if (fmt == 1) {
        const float4* s = (const float4*)src;
        for (; i < n4; i += stride) {
            float4 v = s[i];
            uchar4 o;
            o.x = __nv_fp8_e4m3(v.x).__x;
            o.y = __nv_fp8_e4m3(v.y).__x;
            o.z = __nv_fp8_e4m3(v.z).__x;
            o.w = __nv_fp8_e4m3(v.w).__x;
            d4[i] = o;
        }
    } else if (fmt == 2) {
        const __nv_bfloat162* s = (const __nv_bfloat162*)src;
        for (; i < n4; i += stride) {
            __nv_bfloat162 a = s[i * 2], b = s[i * 2 + 1];
            uchar4 o;
            o.x = __nv_fp8_e4m3(__bfloat162float(a.x)).__x;
            o.y = __nv_fp8_e4m3(__bfloat162float(a.y)).__x;
            o.z = __nv_fp8_e4m3(__bfloat162float(b.x)).__x;
            o.w = __nv_fp8_e4m3(__bfloat162float(b.y)).__x;
            d4[i] = o;
        }
    } else {
        const uchar4* s = (const uchar4*)src;
        for (; i < n4; i += stride) d4[i] = s[i];
    }
}

// ---------------- per-token per-128-group fake-quant of activations ----------------
__global__ void quant_act_kernel(const float* __restrict__ X,
                                 uint8_t* __restrict__ Q,
                                 float* __restrict__ S, int Kdim) {
    const int KB = Kdim >> 7;
    const int g = blockIdx.x;
    const int m = blockIdx.y;
    const int t = threadIdx.x;
    size_t base = (size_t)m * Kdim + (size_t)g * 128;
    float v = X[base + t];
    float a = fabsf(v);
#pragma unroll
    for (int o = 16; o > 0; o >>= 1) a = fmaxf(a, __shfl_xor_sync(0xffffffffu, a, o));
    __shared__ float red[4];
    if ((t & 31) == 0) red[t >> 5] = a;
    __syncthreads();
    float amax = fmaxf(fmaxf(red[0], red[1]), fmaxf(red[2], red[3]));
    float s = fmaxf(amax * (1.0f / 448.0f), 1e-12f);
    float qv = fminf(fmaxf(v / s, -448.0f), 448.0f);
    Q[base + t] = __nv_fp8_e4m3(qv).__x;
    if (t == 0) S[(size_t)m * KB + g] = s;
}

// =================== shared GEMM building blocks ===================
__device__ __forceinline__ uint32_t smem_to_u32(const void* p) {
    uint32_t a;
    asm("{ .reg .u64 t; cvta.to.shared.u64 t, %1; cvt.u32.u64 %0, t; }" : "=r"(a) : "l"(p));
    return a;
}
__device__ __forceinline__ void mma_fp8(float* c, const uint32_t* a, const uint32_t* b) {
    asm volatile(
        "mma.sync.aligned.m16n8k32.row.col.f32.e4m3.e4m3.f32 "
        "{%0,%1,%2,%3},{%4,%5,%6,%7},{%8,%9},{%0,%1,%2,%3};\n"
        : "+f"(c[0]), "+f"(c[1]), "+f"(c[2]), "+f"(c[3])
        : "r"(a[0]), "r"(a[1]), "r"(a[2]), "r"(a[3]), "r"(b[0]), "r"(b[1]));
}
__device__ __forceinline__ void ldsm4(uint32_t* r, uint32_t addr) {
    asm volatile("ldmatrix.sync.aligned.m8n8.x4.shared.b16 {%0,%1,%2,%3},[%4];\n"
                 : "=r"(r[0]), "=r"(r[1]), "=r"(r[2]), "=r"(r[3]) : "r"(addr));
}

#define ROW_BYTES 144    // 128 + 16 pad: conflict-free ldmatrix

// ============== FUSED gate+up GEMM + silu*up + fake-quant ==============
// CTA tile: 64 (M) x 128 (N, one quant group), both gate and up weights.
// 256 threads / 8 warps; warp tile 32(M) x 32(N) per GEMM.
// Fragment double-buffering: ldsm of ks+1 issued before mma of ks so the
// smem-crossbar phase overlaps the tensor phase.

#define FU_THREADS 256
#define FU_A_BYTES (64 * ROW_BYTES)            // 9216
#define FU_B_BYTES (128 * ROW_BYTES)           // 18432
#define FU_STAGE (FU_A_BYTES + 2 * FU_B_BYTES) // 46080
#define FU_NSTAGE 4
#define FU_SMEM (FU_NSTAGE * FU_STAGE)         // 184320

__device__ __forceinline__ void fu_load_stage(
    const uint8_t* __restrict__ A, const uint8_t* __restrict__ Bg,
    const uint8_t* __restrict__ Bu,
    int m0, int n0, int kb, uint32_t stage_smem, int tid) {
    const uint8_t* Ap = A + (size_t)m0 * H_DIM + (size_t)kb * 128;
    const uint8_t* Bgp = Bg + (size_t)n0 * H_DIM + (size_t)kb * 128;
    const uint8_t* Bup = Bu + (size_t)n0 * H_DIM + (size_t)kb * 128;
#pragma unroll
    for (int it = 0; it < 10; it++) {
        int i = it * FU_THREADS + tid;          // 0..2559 16B chunks
        const uint8_t* g;
        uint32_t d;
        if (i < 512) {                          // A: 64 rows x 8 chunks
            int r = i >> 3, col = (i & 7) * 16;
            g = Ap + (size_t)r * H_DIM + col;
            d = stage_smem + (uint32_t)(r * ROW_BYTES + col);
        } else if (i < 1536) {                  // B gate: 128 rows x 8
            int j = i - 512;
            int r = j >> 3, col = (j & 7) * 16;
            g = Bgp + (size_t)r * H_DIM + col;
            d = stage_smem + FU_A_BYTES + (uint32_t)(r * ROW_BYTES + col);
        } else {                                // B up
            int j = i - 1536;
            int r = j >> 3, col = (j & 7) * 16;
            g = Bup + (size_t)r * H_DIM + col;
            d = stage_smem + FU_A_BYTES + FU_B_BYTES + (uint32_t)(r * ROW_BYTES + col);
        }
        asm volatile("cp.async.cg.shared.global [%0], [%1], 16;\n" :: "r"(d), "l"(g));
    }
    asm volatile("cp.async.commit_group;\n" ::: "memory");
}

__global__ void __launch_bounds__(FU_THREADS, 1)
fused_gateup(const uint8_t* __restrict__ A, const float* __restrict__ As,
             const uint8_t* __restrict__ Bg, const float* __restrict__ Bsg,
             const uint8_t* __restrict__ Bu, const float* __restrict__ Bsu,
             uint8_t* __restrict__ Hq, float* __restrict__ Hs) {
    extern __shared__ char smem_raw[];
    const uint32_t sbase = smem_to_u32(smem_raw);

    const int tid = threadIdx.x;
    const int lane = tid & 31;
    const int w = tid >> 5;
    const int wm = (w & 1) * 32;    // 2 m-positions of 32 rows
    const int wn = (w >> 1) * 32;   // 4 n-strips of 32 cols
    const int m0 = blockIdx.x * 64;   // m fastest: A panel stays L2-resident
    const int n0 = blockIdx.y * 128;
    const int nb = blockIdx.y;

    const int a_r = (((lane >> 3) & 1) << 3) + (lane & 7);
    const int a_kb = (lane >> 4) << 4;
    const uint32_t aoff = (uint32_t)((wm + a_r) * ROW_BYTES + a_kb);

    const int g4 = lane >> 3;
    const int b_row = ((g4 >> 1) << 3) + (lane & 7);
    const int b_kb = (g4 & 1) << 4;
    const uint32_t bgoff = (uint32_t)(FU_A_BYTES + (wn + b_row) * ROW_BYTES + b_kb);
    const uint32_t buoff = bgoff + FU_B_BYTES;

    float fcg[2][4][4], fcu[2][4][4], pcg[2][4][4], pcu[2][4][4];
#pragma unroll
    for (int mt = 0; mt < 2; mt++)
#pragma unroll
        for (int nt = 0; nt < 4; nt++)
#pragma unroll
            for (int k2 = 0; k2 < 4; k2++) {
                fcg[mt][nt][k2] = 0.0f; fcu[mt][nt][k2] = 0.0f;
                pcg[mt][nt][k2] = 0.0f; pcu[mt][nt][k2] = 0.0f;
            }

    const int pr0 = m0 + wm + (lane >> 2);
    const float* BsgRow = Bsg + (size_t)nb * KB_H;
    const float* BsuRow = Bsu + (size_t)nb * KB_H;

    fu_load_stage(A, Bg, Bu, m0, n0, 0, sbase + 0 * FU_STAGE, tid);
    fu_load_stage(A, Bg, Bu, m0, n0, 1, sbase + 1 * FU_STAGE, tid);
    fu_load_stage(A, Bg, Bu, m0, n0, 2, sbase + 2 * FU_STAGE, tid);

    float sA[4], sWg = BsgRow[0], sWu = BsuRow[0];
#pragma unroll
    for (int ri = 0; ri < 4; ri++) sA[ri] = As[(size_t)(pr0 + ri * 8) * KB_H + 0];

    // double-buffered fragments
    uint32_t af[2][2][4], bfg[2][4][2], bfu[2][4][2];

    for (int kb = 0; kb < KB_H; kb++) {
        asm volatile("cp.async.wait_group 2;\n" ::: "memory");
        __syncthreads();

        if (kb + 3 < KB_H)
            fu_load_stage(A, Bg, Bu, m0, n0, kb + 3,
                          sbase + (uint32_t)((kb + 3) & 3) * FU_STAGE, tid);
        else
            asm volatile("cp.async.commit_group;\n" ::: "memory");

        float nA[4], nWg = 0.0f, nWu = 0.0f;
        if (kb + 1 < KB_H) {
#pragma unroll
            for (int ri = 0; ri < 4; ri++) nA[ri] = As[(size_t)(pr0 + ri * 8) * KB_H + kb + 1];
            nWg = BsgRow[kb + 1]; nWu = BsuRow[kb + 1];
        } else {
#pragma unroll
            for (int ri = 0; ri < 4; ri++) nA[ri] = 0.0f;
        }

        const uint32_t sa = sbase + (uint32_t)(kb & 3) * FU_STAGE;

        // load frags for ks=0 into slot 0
#pragma unroll
        for (int mt = 0; mt < 2; mt++)
            ldsm4(af[0][mt], sa + aoff + (uint32_t)(mt * 16 * ROW_BYTES));
#pragma unroll
        for (int p = 0; p < 2; p++) {
            uint32_t q[4];
            ldsm4(q, sa + bgoff + (uint32_t)(p * 16 * ROW_BYTES));
            bfg[0][2 * p][0] = q[0]; bfg[0][2 * p][1] = q[1];
            bfg[0][2 * p + 1][0] = q[2]; bfg[0][2 * p + 1][1] = q[3];
            uint32_t q2[4];
            ldsm4(q2, sa + buoff + (uint32_t)(p * 16 * ROW_BYTES));
            bfu[0][2 * p][0] = q2[0]; bfu[0][2 * p][1] = q2[1];
            bfu[0][2 * p + 1][0] = q2[2]; bfu[0][2 * p + 1][1] = q2[3];
        }

#pragma unroll
        for (int ks = 0; ks < 4; ks++) {
            const int cur = ks & 1, nxt = cur ^ 1;
            if (ks < 3) {   // issue ldsm for ks+1 BEFORE the mma chain of ks
#pragma unroll
                for (int mt = 0; mt < 2; mt++)
                    ldsm4(af[nxt][mt],
                          sa + aoff + (uint32_t)(mt * 16 * ROW_BYTES + (ks + 1) * 32));
#pragma unroll
                for (int p = 0; p < 2; p++) {
                    uint32_t q[4];
                    ldsm4(q, sa + bgoff + (uint32_t)(p * 16 * ROW_BYTES + (ks + 1) * 32));
                    bfg[nxt][2 * p][0] = q[0]; bfg[nxt][2 * p][1] = q[1];
                    bfg[nxt][2 * p + 1][0] = q[2]; bfg[nxt][2 * p + 1][1] = q[3];
                    uint32_t q2[4];
                    ldsm4(q2, sa + buoff + (uint32_t)(p * 16 * ROW_BYTES + (ks + 1) * 32));
                    bfu[nxt][2 * p][0] = q2[0]; bfu[nxt][2 * p][1] = q2[1];
                    bfu[nxt][2 * p + 1][0] = q2[2]; bfu[nxt][2 * p + 1][1] = q2[3];
                }
            }
#pragma unroll
            for (int mt = 0; mt < 2; mt++)
#pragma unroll
                for (int nt = 0; nt < 4; nt++) {
                    mma_fp8(pcg[mt][nt], af[cur][mt], bfg[cur][nt]);
                    mma_fp8(pcu[mt][nt], af[cur][mt], bfu[cur][nt]);
                }
        }

        // promote with fp32 scales
#pragma unroll
        for (int mt = 0; mt < 2; mt++) {
            float sg0 = sA[mt * 2] * sWg,     su0 = sA[mt * 2] * sWu;
            float sg1 = sA[mt * 2 + 1] * sWg, su1 = sA[mt * 2 + 1] * sWu;
#pragma unroll
            for (int nt = 0; nt < 4; nt++) {
                fcg[mt][nt][0] += sg0 * pcg[mt][nt][0];
                fcg[mt][nt][1] += sg0 * pcg[mt][nt][1];
                fcg[mt][nt][2] += sg1 * pcg[mt][nt][2];
                fcg[mt][nt][3] += sg1 * pcg[mt][nt][3];
                fcu[mt][nt][0] += su0 * pcu[mt][nt][0];
                fcu[mt][nt][1] += su0 * pcu[mt][nt][1];
                fcu[mt][nt][2] += su1 * pcu[mt][nt][2];
                fcu[mt][nt][3] += su1 * pcu[mt][nt][3];
#pragma unroll
                for (int k2 = 0; k2 < 4; k2++) { pcg[mt][nt][k2] = 0.0f; pcu[mt][nt][k2] = 0.0f; }
            }
        }
#pragma unroll
        for (int ri = 0; ri < 4; ri++) sA[ri] = nA[ri];
        sWg = nWg; sWu = nWu;
    }

    // ---------- fused epilogue: hidden = silu(g)*u, per-row amax, quantize ----------
    float lmax[4] = {0.0f, 0.0f, 0.0f, 0.0f};
#pragma unroll
    for (int mt = 0; mt < 2; mt++)
#pragma unroll
        for (int nt = 0; nt < 4; nt++)
#pragma unroll
            for (int k2 = 0; k2 < 4; k2++) {
                float gv = fcg[mt][nt][k2];
                float h = (gv / (1.0f + expf(-gv))) * fcu[mt][nt][k2];
                fcg[mt][nt][k2] = h;
                int ri = mt * 2 + (k2 >> 1);
                lmax[ri] = fmaxf(lmax[ri], fabsf(h));
            }
#pragma unroll
    for (int off = 1; off <= 2; off <<= 1)
#pragma unroll
        for (int ri = 0; ri < 4; ri++)
            lmax[ri] = fmaxf(lmax[ri], __shfl_xor_sync(0xffffffffu, lmax[ri], off));

    float* rmax = (float*)smem_raw;   // [4 strips][64 rows]
    __syncthreads();
    if ((lane & 3) == 0) {
#pragma unroll
        for (int ri = 0; ri < 4; ri++)
            rmax[(w >> 1) * 64 + wm + ri * 8 + (lane >> 2)] = lmax[ri];
    }
    __syncthreads();

    float scale[4];
#pragma unroll
    for (int ri = 0; ri < 4; ri++) {
        int rl = wm + ri * 8 + (lane >> 2);
        float amax = fmaxf(fmaxf(rmax[rl], rmax[64 + rl]),
                           fmaxf(rmax[128 + rl], rmax[192 + rl]));
        scale[ri] = fmaxf(amax * (1.0f / 448.0f), 1e-12f);
    }

#pragma unroll
    for (int mt = 0; mt < 2; mt++)
#pragma unroll
        for (int rh = 0; rh < 2; rh++) {
            int ri = mt * 2 + rh;
            int row = m0 + wm + ri * 8 + (lane >> 2);
            float s = scale[ri];
            if ((w >> 1) == 0 && (lane & 3) == 0)
                Hs[(size_t)row * KB_I + nb] = s;
#pragma unroll
            for (int nt = 0; nt < 4; nt++) {
                float h0 = fcg[mt][nt][rh * 2 + 0];
                float h1 = fcg[mt][nt][rh * 2 + 1];
                float q0 = fminf(fmaxf(h0 / s, -448.0f), 448.0f);
                float q1 = fminf(fmaxf(h1 / s, -448.0f), 448.0f);
                uchar2 o;
                o.x = __nv_fp8_e4m3(q0).__x;
                o.y = __nv_fp8_e4m3(q1).__x;
                int col = n0 + wn + nt * 8 + (lane & 3) * 2;
                *(uchar2*)(Hq + (size_t)row * I_DIM + col) = o;
            }
        }
}

// =================== down GEMM (256 threads, warp 32x64, dbl-buffered frags) ===================
#define GEMM_THREADS 256
#define STAGE_A (128 * ROW_BYTES)     // 18432
#define STAGE_BYTES (2 * STAGE_A)     // 36864
#define NSTAGE 5
#define GEMM_SMEM (NSTAGE * STAGE_BYTES)   // 184320

__device__ __forceinline__ void load_stage(
    const uint8_t* __restrict__ A, const uint8_t* __restrict__ B,
    int Kdim, int m0, int n0, int kb, uint32_t stage_smem, int tid) {
    const uint8_t* Ag = A + (size_t)m0 * Kdim + (size_t)kb * 128;
    const uint8_t* Bg = B + (size_t)n0 * Kdim + (size_t)kb * 128;
#pragma unroll
    for (int it = 0; it < 8; it++) {
        int i = it * GEMM_THREADS + tid;
        int half = i >> 10;
        int c = i & 1023;
        int r = c >> 3;
        int col = (c & 7) * 16;
        const uint8_t* g = half ? (Bg + (size_t)r * Kdim + col)
                                : (Ag + (size_t)r * Kdim + col);
        uint32_t d = stage_smem + (uint32_t)half * STAGE_A + (uint32_t)(r * ROW_BYTES + col);
        asm volatile("cp.async.cg.shared.global [%0], [%1], 16;\n" :: "r"(d), "l"(g));
    }
    asm volatile("cp.async.commit_group;\n" ::: "memory");
}

__global__ void __launch_bounds__(GEMM_THREADS, 1)
gemm_fp8(const uint8_t* __restrict__ A, const float* __restrict__ As,
         const uint8_t* __restrict__ B, const float* __restrict__ Bs,
         float* __restrict__ C, int Ndim, int Kdim) {
    extern __shared__ char smem_raw[];
    const uint32_t sbase = smem_to_u32(smem_raw);

    const int KB = Kdim >> 7;
    const int tid = threadIdx.x;
    const int lane = tid & 31;
    const int w = tid >> 5;
    const int wm = (w & 3) * 32;   // 4 m-positions of 32 rows
    const int wn = (w >> 2) * 64;  // 2 n-halves of 64 cols
    const int m0 = blockIdx.y * 128;
    const int n0 = blockIdx.x * 128;
    const int nb = blockIdx.x;

    const int a_r = (((lane >> 3) & 1) << 3) + (lane & 7);
    const int a_kb = (lane >> 4) << 4;
    const uint32_t aoff = (uint32_t)((wm + a_r) * ROW_BYTES + a_kb);

    const int g4 = lane >> 3;
    const int b_row = ((g4 >> 1) << 3) + (lane & 7);
    const int b_kb = (g4 & 1) << 4;
    const uint32_t boff = (uint32_t)(STAGE_A + (wn + b_row) * ROW_BYTES + b_kb);

    float fc[2][8][4], pc[2][8][4];
#pragma unroll
    for (int mt = 0; mt < 2; mt++)
#pragma unroll
        for (int nt = 0; nt < 8; nt++)
#pragma unroll
            for (int k = 0; k < 4; k++) { fc[mt][nt][k] = 0.0f; pc[mt][nt][k] = 0.0f; }

    const int pr0 = m0 + wm + (lane >> 2);
    const float* BsRow = Bs + (size_t)nb * KB;

    load_stage(A, B, Kdim, m0, n0, 0, sbase + 0 * STAGE_BYTES, tid);
    load_stage(A, B, Kdim, m0, n0, 1, sbase + 1 * STAGE_BYTES, tid);
    load_stage(A, B, Kdim, m0, n0, 2, sbase + 2 * STAGE_BYTES, tid);
    load_stage(A, B, Kdim, m0, n0, 3, sbase + 3 * STAGE_BYTES, tid);

    float sA[4];   // scales for rows pr0 + ri*8 (ri = mt*2 + rh)
#pragma unroll
    for (int ri = 0; ri < 4; ri++) sA[ri] = As[(size_t)(pr0 + ri * 8) * KB + 0];
    float sW = BsRow[0];

    uint32_t af[2][2][4], bf[2][8][2];   // double-buffered fragments

    for (int kb = 0; kb < KB; kb++) {
        asm volatile("cp.async.wait_group 3;\n" ::: "memory");
        __syncthreads();

        if (kb + 4 < KB)
            load_stage(A, B, Kdim, m0, n0, kb + 4,
                       sbase + (uint32_t)((kb + 4) % NSTAGE) * STAGE_BYTES, tid);
        else
            asm volatile("cp.async.commit_group;\n" ::: "memory");

        float nA[4], nW = 0.0f;
        if (kb + 1 < KB) {
#pragma unroll
            for (int ri = 0; ri < 4; ri++) nA[ri] = As[(size_t)(pr0 + ri * 8) * KB + kb + 1];
            nW = BsRow[kb + 1];
        } else {
#pragma unroll
            for (int ri = 0; ri < 4; ri++) nA[ri] = 0.0f;
        }

        const uint32_t sa = sbase + (uint32_t)(kb % NSTAGE) * STAGE_BYTES;

        // frags for ks=0 into slot 0
#pragma unroll
        for (int mt = 0; mt < 2; mt++)
            ldsm4(af[0][mt], sa + aoff + (uint32_t)(mt * 16 * ROW_BYTES));
#pragma unroll
        for (int p = 0; p < 4; p++) {
            uint32_t q[4];
            ldsm4(q, sa + boff + (uint32_t)(p * 16 * ROW_BYTES));
            bf[0][2 * p][0] = q[0]; bf[0][2 * p][1] = q[1];
            bf[0][2 * p + 1][0] = q[2]; bf[0][2 * p + 1][1] = q[3];
        }

#pragma unroll
        for (int ks = 0; ks < 4; ks++) {
            const int cur = ks & 1, nxt = cur ^ 1;
            if (ks < 3) {   // ldsm for ks+1 before mma chain of ks
#pragma unroll
                for (int mt = 0; mt < 2; mt++)
                    ldsm4(af[nxt][mt],
                          sa + aoff + (uint32_t)(mt * 16 * ROW_BYTES + (ks + 1) * 32));
#pragma unroll
                for (int p = 0; p < 4; p++) {
                    uint32_t q[4];
                    ldsm4(q, sa + boff + (uint32_t)(p * 16 * ROW_BYTES + (ks + 1) * 32));
                    bf[nxt][2 * p][0] = q[0]; bf[nxt][2 * p][1] = q[1];
                    bf[nxt][2 * p + 1][0] = q[2]; bf[nxt][2 * p + 1][1] = q[3];
                }
            }
#pragma unroll
            for (int mt = 0; mt < 2; mt++)
#pragma unroll
                for (int nt = 0; nt < 8; nt++)
                    mma_fp8(pc[mt][nt], af[cur][mt], bf[cur][nt]);
        }

        // promote this 128-K block with fp32 scales
#pragma unroll
        for (int mt = 0; mt < 2; mt++) {
            float s0 = sA[mt * 2] * sW;
            float s1 = sA[mt * 2 + 1] * sW;
#pragma unroll
            for (int nt = 0; nt < 8; nt++) {
                fc[mt][nt][0] += s0 * pc[mt][nt][0];
                fc[mt][nt][1] += s0 * pc[mt][nt][1];
                fc[mt][nt][2] += s1 * pc[mt][nt][2];
                fc[mt][nt][3] += s1 * pc[mt][nt][3];
                pc[mt][nt][0] = 0.0f; pc[mt][nt][1] = 0.0f;
                pc[mt][nt][2] = 0.0f; pc[mt][nt][3] = 0.0f;
            }
        }
#pragma unroll
        for (int ri = 0; ri < 4; ri++) sA[ri] = nA[ri];
        sW = nW;
    }

    // epilogue
#pragma unroll
    for (int mt = 0; mt < 2; mt++) {
        int r0 = pr0 + mt * 16;
#pragma unroll
        for (int nt = 0; nt < 8; nt++) {
            int c0 = n0 + wn + nt * 8 + (lane & 3) * 2;
            *(float2*)(C + (size_t)r0 * Ndim + c0) =
                make_float2(fc[mt][nt][0], fc[mt][nt][1]);
            *(float2*)(C + (size_t)(r0 + 8) * Ndim + c0) =
                make_float2(fc[mt][nt][2], fc[mt][nt][3]);
        }
    }
}

// ---------------- launch ----------------
extern "C" void kernel_launch(void* const* d_in, const int* in_sizes, int n_in,
                              void* d_out, int out_size) {
    (void)in_sizes; (void)n_in; (void)out_size;
    const float* x  = (const float*)d_in[0];
    const void*  gw = d_in[1];
    const float* gs = (const float*)d_in[2];
    const void*  uw = d_in[3];
    const float* us = (const float*)d_in[4];
    const void*  dw = d_in[5];
    const float* ds = (const float*)d_in[6];
    float* out = (float*)d_out;

    static bool init = false;
    static void *pAq, *pAs, *pWg, *pWu, *pWd, *pHq, *pHs;
    if (!init) {
        cudaGetSymbolAddress(&pAq, g_Aq);
        cudaGetSymbolAddress(&pAs, g_As);
        cudaGetSymbolAddress(&pWg, g_Wg);
        cudaGetSymbolAddress(&pWu, g_Wu);
        cudaGetSymbolAddress(&pWd, g_Wd);
        cudaGetSymbolAddress(&pHq, g_Hq);
        cudaGetSymbolAddress(&pHs, g_Hs);
        cudaFuncSetAttribute(fused_gateup,
                             cudaFuncAttributeMaxDynamicSharedMemorySize, FU_SMEM);
        cudaFuncSetAttribute(gemm_fp8,
                             cudaFuncAttributeMaxDynamicSharedMemorySize, GEMM_SMEM);
        init = true;
    }

    detect_kernel<<<1, 256>>>(gw);                                                   // 0
    convert_w_kernel<<<2048, 256>>>(gw, (uint8_t*)pWg, (size_t)I_DIM * H_DIM / 4);   // 1
    convert_w_kernel<<<2048, 256>>>(uw, (uint8_t*)pWu, (size_t)I_DIM * H_DIM / 4);   // 2
    convert_w_kernel<<<2048, 256>>>(dw, (uint8_t*)pWd, (size_t)H_DIM * I_DIM / 4);   // 3
    quant_act_kernel<<<dim3(KB_H, M_DIM), 128>>>(x, (uint8_t*)pAq, (float*)pAs, H_DIM); // 4

    dim3 fgrid(M_DIM / 64, I_DIM / 128);   // m fastest -> A panel L2-resident
    fused_gateup<<<fgrid, FU_THREADS, FU_SMEM>>>(                                    // 5
        (uint8_t*)pAq, (float*)pAs, (uint8_t*)pWg, gs, (uint8_t*)pWu, us,
        (uint8_t*)pHq, (float*)pHs);

    dim3 grid2(H_DIM / 128, M_DIM / 128);
    gemm_fp8<<<grid2, GEMM_THREADS, GEMM_SMEM>>>(                                    // 6
        (uint8_t*)pHq, (float*)pHs, (uint8_t*)pWd, ds, out, H_DIM, I_DIM);
}

// round 17
// speedup vs baseline: 1.0252x; 1.0252x over previous
#include <cuda_runtime.h>
#include <cuda_bf16.h>
#include <cuda_fp8.h>
#include <math.h>
#include <stdint.h>

// Problem shape: x[M,H], gate/up [I,H], down [H,I]
#define M_DIM 4096
#define H_DIM 4096
#define I_DIM 14336
#define KB_H (H_DIM / 128)   // 32
#define KB_I (I_DIM / 128)   // 112

// ---------------- scratch (device globals; no allocation) ----------------
__device__ uint8_t g_Aq[(size_t)M_DIM * H_DIM];     // e4m3 codes of quantized x
__device__ float   g_As[(size_t)M_DIM * KB_H];
__device__ uint8_t g_Wg[(size_t)I_DIM * H_DIM];     // e4m3 weight codes
__device__ uint8_t g_Wu[(size_t)I_DIM * H_DIM];
__device__ uint8_t g_Wd[(size_t)H_DIM * I_DIM];
__device__ float   g_gate[(size_t)M_DIM * I_DIM];   // fp32 gate (exact)
__device__ uint8_t g_Hq[(size_t)M_DIM * I_DIM];     // e4m3 hidden codes
__device__ float   g_Hs[(size_t)M_DIM * KB_I];
__device__ int     g_wfmt;   // 0 = raw e4m3 bytes, 1 = float32, 2 = bfloat16

// ---------------- weight dtype detection (device-side, deterministic) ----------------
__global__ void detect_kernel(const void* __restrict__ w) {
    __shared__ int c32, c16;
    int t = threadIdx.x;
    if (t == 0) { c32 = 0; c16 = 0; }
    __syncthreads();
    const float* f = (const float*)w;
    const __nv_bfloat16* b = (const __nv_bfloat16*)w;
    int l32 = 0, l16 = 0;
    for (int i = t; i < 16384; i += 256) {
        float v = f[i];
        if (fabsf(v) <= 448.0f) l32++;
        float u = __bfloat162float(b[i]);
        if (fabsf(u) <= 448.0f) l16++;
    }
    atomicAdd(&c32, l32);
    atomicAdd(&c16, l16);
    __syncthreads();
    if (t == 0) {
        int fmt = 0;
        if (c32 >= 16056) fmt = 1;
        else if (c16 >= 16056) fmt = 2;
        g_wfmt = fmt;
    }
}

// ---------------- weight convert: all 3 weights in one launch ----------------
// Each weight has the same element count (I*H == H*I).
__device__ __forceinline__ void conv_seg(const void* src, uint8_t* dst, size_t i, int fmt) {
    uchar4* d4 = (uchar4*)dst;
    if (fmt == 1) {
        float4 v = ((const float4*)src)[i];
        uchar4 o;
        o.x = __nv_fp8_e4m3(v.x).__x;
        o.y = __nv_fp8_e4m3(v.y).__x;
        o.z = __nv_fp8_e4m3(v.z).__x;
        o.w = __nv_fp8_e4m3(v.w).__x;
        d4[i] = o;
    } else if (fmt == 2) {
        const __nv_bfloat162* s = (const __nv_bfloat162*)src;
        __nv_bfloat162 a = s[i * 2], b = s[i * 2 + 1];
        uchar4 o;
        o.x = __nv_fp8_e4m3(__bfloat162float(a.x)).__x;
        o.y = __nv_fp8_e4m3(__bfloat162float(a.y)).__x;
        o.z = __nv_fp8_e4m3(__bfloat162float(b.x)).__x;
        o.w = __nv_fp8_e4m3(__bfloat162float(b.y)).__x;
        d4[i] = o;
    } else {
        d4[i] = ((const uchar4*)src)[i];
    }
}

__global__ void convert_w3_kernel(const void* __restrict__ s0, uint8_t* __restrict__ d0,
                                  const void* __restrict__ s1, uint8_t* __restrict__ d1,
                                  const void* __restrict__ s2, uint8_t* __restrict__ d2,
                                  size_t n4) {   // n4 per weight
    int fmt = g_wfmt;
    size_t i = (size_t)blockIdx.x * blockDim.x + threadIdx.x;
    size_t stride = (size_t)gridDim.x * blockDim.x;
    size_t total = 3 * n4;
    for (; i < total; i += stride) {
        if (i < n4)            conv_seg(s0, d0, i, fmt);
        else if (i < 2 * n4)   conv_seg(s1, d1, i - n4, fmt);
        else                   conv_seg(s2, d2, i - 2 * n4, fmt);
    }
}

// ---------------- per-token per-128-group fake-quant of activations ----------------
__global__ void quant_act_kernel(const float* __restrict__ X,
                                 uint8_t* __restrict__ Q,
                                 float* __restrict__ S, int Kdim) {
    const int KB = Kdim >> 7;
    const int g = blockIdx.x;
    const int m = blockIdx.y;
    const int t = threadIdx.x;
    size_t base = (size_t)m * Kdim + (size_t)g * 128;
    float v = X[base + t];
    float a = fabsf(v);
#pragma unroll
    for (int o = 16; o > 0; o >>= 1) a = fmaxf(a, __shfl_xor_sync(0xffffffffu, a, o));
    __shared__ float red[4];
    if ((t & 31) == 0) red[t >> 5] = a;
    __syncthreads();
    float amax = fmaxf(fmaxf(red[0], red[1]), fmaxf(red[2], red[3]));
    float s = fmaxf(amax * (1.0f / 448.0f), 1e-12f);
    float qv = fminf(fmaxf(v / s, -448.0f), 448.0f);
    Q[base + t] = __nv_fp8_e4m3(qv).__x;
    if (t == 0) S[(size_t)m * KB + g] = s;
}

// =================== FP8 mma.sync block-scaled GEMM (R10 core) ===================
#define GEMM_THREADS 512
#define ROW_BYTES 144                 // 128 + 16 pad: conflict-free ldmatrix
#define STAGE_A (128 * ROW_BYTES)     // 18432
#define STAGE_BYTES (2 * STAGE_A)     // 36864
#define NSTAGE 5
#define GEMM_SMEM (NSTAGE * STAGE_BYTES)   // 184320

__device__ __forceinline__ uint32_t smem_to_u32(const void* p) {
    uint32_t a;
    asm("{ .reg .u64 t; cvta.to.shared.u64 t, %1; cvt.u32.u64 %0, t; }" : "=r"(a) : "l"(p));
    return a;
}
__device__ __forceinline__ void mma_fp8(float* c, const uint32_t* a, const uint32_t* b) {
    asm volatile(
        "mma.sync.aligned.m16n8k32.row.col.f32.e4m3.e4m3.f32 "
        "{%0,%1,%2,%3},{%4,%5,%6,%7},{%8,%9},{%0,%1,%2,%3};\n"
        : "+f"(c[0]), "+f"(c[1]), "+f"(c[2]), "+f"(c[3])
        : "r"(a[0]), "r"(a[1]), "r"(a[2]), "r"(a[3]), "r"(b[0]), "r"(b[1]));
}
__device__ __forceinline__ void ldsm4(uint32_t* r, uint32_t addr) {
    asm volatile("ldmatrix.sync.aligned.m8n8.x4.shared.b16 {%0,%1,%2,%3},[%4];\n"
                 : "=r"(r[0]), "=r"(r[1]), "=r"(r[2]), "=r"(r[3]) : "r"(addr));
}

__device__ __forceinline__ void load_stage(
    const uint8_t* __restrict__ A, const uint8_t* __restrict__ B,
    int Kdim, int m0, int n0, int kb, uint32_t stage_smem, int tid) {
    const uint8_t* Ag = A + (size_t)m0 * Kdim + (size_t)kb * 128;
    const uint8_t* Bg = B + (size_t)n0 * Kdim + (size_t)kb * 128;
#pragma unroll
    for (int it = 0; it < 4; it++) {
        int i = it * GEMM_THREADS + tid;
        int half = i >> 10;
        int c = i & 1023;
        int r = c >> 3;
        int col = (c & 7) * 16;
        const uint8_t* g = half ? (Bg + (size_t)r * Kdim + col)
                                : (Ag + (size_t)r * Kdim + col);
        uint32_t d = stage_smem + (uint32_t)half * STAGE_A + (uint32_t)(r * ROW_BYTES + col);
        asm volatile("cp.async.cg.shared.global [%0], [%1], 16;\n" :: "r"(d), "l"(g));
    }
    asm volatile("cp.async.commit_group;\n" ::: "memory");
}

// Shared mainloop; epilogue selected by template flag.
// EPI = 0: plain fp32 store to C.
// EPI = 1: read gate fp32 from Gin at matching coords, h = silu(g)*u,
//          per-row amax over this CTA's 128 cols (one quant group),
//          quantize to e4m3, write Hq codes + Hs scales.
template <int EPI>
__global__ void __launch_bounds__(GEMM_THREADS, 1)
gemm_fp8(const uint8_t* __restrict__ A, const float* __restrict__ As,
         const uint8_t* __restrict__ B, const float* __restrict__ Bs,
         float* __restrict__ C, const float* __restrict__ Gin,
         uint8_t* __restrict__ Hq, float* __restrict__ Hs,
         int Ndim, int Kdim) {
    extern __shared__ char smem_raw[];
    const uint32_t sbase = smem_to_u32(smem_raw);

    const int KB = Kdim >> 7;
    const int tid = threadIdx.x;
    const int lane = tid & 31;
    const int w = tid >> 5;
    const int wm = (w & 7) * 16;
    const int wn = (w >> 3) * 64;
    const int m0 = blockIdx.y * 128;
    const int n0 = blockIdx.x * 128;
    const int nb = blockIdx.x;

    const int a_r = (((lane >> 3) & 1) << 3) + (lane & 7);
    const int a_kb = (lane >> 4) << 4;
    const uint32_t aoff = (uint32_t)((wm + a_r) * ROW_BYTES + a_kb);

    const int g4 = lane >> 3;
    const int b_row = ((g4 >> 1) << 3) + (lane & 7);
    const int b_kb = (g4 & 1) << 4;
    const uint32_t boff = (uint32_t)(STAGE_A + (wn + b_row) * ROW_BYTES + b_kb);

    float fc[8][4], pc[8][4];
#pragma unroll
    for (int j = 0; j < 8; j++)
#pragma unroll
        for (int k = 0; k < 4; k++) { fc[j][k] = 0.0f; pc[j][k] = 0.0f; }

    const int pr0 = m0 + wm + (lane >> 2);
    const float* AsR0 = As + (size_t)pr0 * KB;
    const float* AsR1 = As + (size_t)(pr0 + 8) * KB;
    const float* BsRow = Bs + (size_t)nb * KB;

    load_stage(A, B, Kdim, m0, n0, 0, sbase + 0 * STAGE_BYTES, tid);
    load_stage(A, B, Kdim, m0, n0, 1, sbase + 1 * STAGE_BYTES, tid);
    load_stage(A, B, Kdim, m0, n0, 2, sbase + 2 * STAGE_BYTES, tid);
    load_stage(A, B, Kdim, m0, n0, 3, sbase + 3 * STAGE_BYTES, tid);

    float sA0 = AsR0[0], sA1 = AsR1[0], sW = BsRow[0];

    for (int kb = 0; kb < KB; kb++) {
        asm volatile("cp.async.wait_group 3;\n" ::: "memory");
        __syncthreads();

        if (kb + 4 < KB)
            load_stage(A, B, Kdim, m0, n0, kb + 4,
                       sbase + (uint32_t)((kb + 4) % NSTAGE) * STAGE_BYTES, tid);
        else
            asm volatile("cp.async.commit_group;\n" ::: "memory");

        float nA0 = 0.0f, nA1 = 0.0f, nW = 0.0f;
        if (kb + 1 < KB) { nA0 = AsR0[kb + 1]; nA1 = AsR1[kb + 1]; nW = BsRow[kb + 1]; }

        const uint32_t sa = sbase + (uint32_t)(kb % NSTAGE) * STAGE_BYTES;
#pragma unroll
        for (int ks = 0; ks < 4; ks++) {
            uint32_t af[4], bf[8][2];
            ldsm4(af, sa + aoff + (uint32_t)(ks * 32));
#pragma unroll
            for (int p = 0; p < 2; p++) {
                uint32_t q[4];
                ldsm4(q, sa + boff + (uint32_t)(p * 32 * ROW_BYTES) + (uint32_t)(ks * 32));
                bf[4 * p + 0][0] = q[0]; bf[4 * p + 0][1] = q[1];
                bf[4 * p + 1][0] = q[2]; bf[4 * p + 1][1] = q[3];
                uint32_t q2[4];
                ldsm4(q2, sa + boff + (uint32_t)((p * 32 + 16) * ROW_BYTES) + (uint32_t)(ks * 32));
                bf[4 * p + 2][0] = q2[0]; bf[4 * p + 2][1] = q2[1];
                bf[4 * p + 3][0] = q2[2]; bf[4 * p + 3][1] = q2[3];
            }
#pragma unroll
            for (int nt = 0; nt < 8; nt++)
                mma_fp8(pc[nt], af, bf[nt]);
        }

        float s0 = sA0 * sW;
        float s1 = sA1 * sW;
#pragma unroll
        for (int nt = 0; nt < 8; nt++) {
            fc[nt][0] += s0 * pc[nt][0];
            fc[nt][1] += s0 * pc[nt][1];
            fc[nt][2] += s1 * pc[nt][2];
            fc[nt][3] += s1 * pc[nt][3];
            pc[nt][0] = 0.0f; pc[nt][1] = 0.0f;
            pc[nt][2] = 0.0f; pc[nt][3] = 0.0f;
        }
        sA0 = nA0; sA1 = nA1; sW = nW;
    }

    if constexpr (EPI == 0) {
        // plain fp32 epilogue
#pragma unroll
        for (int nt = 0; nt < 8; nt++) {
            int c0 = n0 + wn + nt * 8 + (lane & 3) * 2;
            *(float2*)(C + (size_t)pr0 * Ndim + c0) = make_float2(fc[nt][0], fc[nt][1]);
            *(float2*)(C + (size_t)(pr0 + 8) * Ndim + c0) = make_float2(fc[nt][2], fc[nt][3]);
        }
    } else {
        // fused silu(g)*u + per-row fake-quant epilogue.
        // fc holds exact fp32 up values; gate read from Gin (exact fp32).
        float lmax0 = 0.0f, lmax1 = 0.0f;
#pragma unroll
        for (int nt = 0; nt < 8; nt++) {
            int c0 = n0 + wn + nt * 8 + (lane & 3) * 2;
            float2 gv0 = *(const float2*)(Gin + (size_t)pr0 * Ndim + c0);
            float2 gv1 = *(const float2*)(Gin + (size_t)(pr0 + 8) * Ndim + c0);
            float h00 = (gv0.x / (1.0f + expf(-gv0.x))) * fc[nt][0];
            float h01 = (gv0.y / (1.0f + expf(-gv0.y))) * fc[nt][1];
            float h10 = (gv1.x / (1.0f + expf(-gv1.x))) * fc[nt][2];
            float h11 = (gv1.y / (1.0f + expf(-gv1.y))) * fc[nt][3];
            fc[nt][0] = h00; fc[nt][1] = h01; fc[nt][2] = h10; fc[nt][3] = h11;
            lmax0 = fmaxf(lmax0, fmaxf(fabsf(h00), fabsf(h01)));
            lmax1 = fmaxf(lmax1, fmaxf(fabsf(h10), fabsf(h11)));
        }
        // reduce amax over the quad (lane&3 spans the 8 cols per nt with pairs)
#pragma unroll
        for (int off = 1; off <= 2; off <<= 1) {
            lmax0 = fmaxf(lmax0, __shfl_xor_sync(0xffffffffu, lmax0, off));
            lmax1 = fmaxf(lmax1, __shfl_xor_sync(0xffffffffu, lmax1, off));
        }
        // cross-warp (two n-halves) reduction via smem; mainloop smem is dead
        // after the __syncthreads below.
        float* rmax = (float*)smem_raw;   // [2 halves][128 rows]
        __syncthreads();
        if ((lane & 3) == 0) {
            rmax[(w >> 3) * 128 + wm + (lane >> 2)] = lmax0;
            rmax[(w >> 3) * 128 + wm + 8 + (lane >> 2)] = lmax1;
        }
        __syncthreads();
        int rl0 = wm + (lane >> 2);
        float am0 = fmaxf(rmax[rl0], rmax[128 + rl0]);
        float am1 = fmaxf(rmax[rl0 + 8], rmax[128 + rl0 + 8]);
        float s0 = fmaxf(am0 * (1.0f / 448.0f), 1e-12f);
        float s1 = fmaxf(am1 * (1.0f / 448.0f), 1e-12f);
        if ((w >> 3) == 0 && (lane & 3) == 0) {
            Hs[(size_t)pr0 * KB_I + nb] = s0;
            Hs[(size_t)(pr0 + 8) * KB_I + nb] = s1;
        }
#pragma unroll
        for (int nt = 0; nt < 8; nt++) {
            int c0 = n0 + wn + nt * 8 + (lane & 3) * 2;
            float q00 = fminf(fmaxf(fc[nt][0] / s0, -448.0f), 448.0f);
            float q01 = fminf(fmaxf(fc[nt][1] / s0, -448.0f), 448.0f);
            float q10 = fminf(fmaxf(fc[nt][2] / s1, -448.0f), 448.0f);
            float q11 = fminf(fmaxf(fc[nt][3] / s1, -448.0f), 448.0f);
            uchar2 o0, o1;
            o0.x = __nv_fp8_e4m3(q00).__x;
            o0.y = __nv_fp8_e4m3(q01).__x;
            o1.x = __nv_fp8_e4m3(q10).__x;
            o1.y = __nv_fp8_e4m3(q11).__x;
            *(uchar2*)(Hq + (size_t)pr0 * Ndim + c0) = o0;
            *(uchar2*)(Hq + (size_t)(pr0 + 8) * Ndim + c0) = o1;
        }
    }
}

// ---------------- launch ----------------
extern "C" void kernel_launch(void* const* d_in, const int* in_sizes, int n_in,
                              void* d_out, int out_size) {
    (void)in_sizes; (void)n_in; (void)out_size;
    const float* x  = (const float*)d_in[0];
    const void*  gw = d_in[1];
    const float* gs = (const float*)d_in[2];
    const void*  uw = d_in[3];
    const float* us = (const float*)d_in[4];
    const void*  dw = d_in[5];
    const float* ds = (const float*)d_in[6];
    float* out = (float*)d_out;

    static bool init = false;
    static void *pAq, *pAs, *pWg, *pWu, *pWd, *pG, *pHq, *pHs;
    if (!init) {
        cudaGetSymbolAddress(&pAq, g_Aq);
        cudaGetSymbolAddress(&pAs, g_As);
        cudaGetSymbolAddress(&pWg, g_Wg);
        cudaGetSymbolAddress(&pWu, g_Wu);
        cudaGetSymbolAddress(&pWd, g_Wd);
        cudaGetSymbolAddress(&pG,  g_gate);
        cudaGetSymbolAddress(&pHq, g_Hq);
        cudaGetSymbolAddress(&pHs, g_Hs);
        cudaFuncSetAttribute(gemm_fp8<0>,
                             cudaFuncAttributeMaxDynamicSharedMemorySize, GEMM_SMEM);
        cudaFuncSetAttribute(gemm_fp8<1>,
                             cudaFuncAttributeMaxDynamicSharedMemorySize, GEMM_SMEM);
        init = true;
    }

    const size_t n4 = (size_t)I_DIM * H_DIM / 4;   // same for all three weights

    detect_kernel<<<1, 256>>>(gw);
    convert_w3_kernel<<<6144, 256>>>(gw, (uint8_t*)pWg, uw, (uint8_t*)pWu,
                                     dw, (uint8_t*)pWd, n4);
    quant_act_kernel<<<dim3(KB_H, M_DIM), 128>>>(x, (uint8_t*)pAq, (float*)pAs, H_DIM);

    dim3 grid1(I_DIM / 128, M_DIM / 128);
    // gate GEMM: exact fp32 out
    gemm_fp8<0><<<grid1, GEMM_THREADS, GEMM_SMEM>>>(
        (uint8_t*)pAq, (float*)pAs, (uint8_t*)pWg, gs,
        (float*)pG, nullptr, nullptr, nullptr, I_DIM, H_DIM);
    // up GEMM with fused silu*gate + fake-quant epilogue
    gemm_fp8<1><<<grid1, GEMM_THREADS, GEMM_SMEM>>>(
        (uint8_t*)pAq, (float*)pAs, (uint8_t*)pWu, us,
        nullptr, (const float*)pG, (uint8_t*)pHq, (float*)pHs, I_DIM, H_DIM);

    dim3 grid2(H_DIM / 128, M_DIM / 128);
    gemm_fp8<0><<<grid2, GEMM_THREADS, GEMM_SMEM>>>(
        (uint8_t*)pHq, (float*)pHs, (uint8_t*)pWd, ds,
        out, nullptr, nullptr, nullptr, H_DIM, I_DIM);
}